// round 3
// baseline (speedup 1.0000x reference)
#include <cuda_runtime.h>
#include <cstddef>

#define NCTA 296
#define NTHR 128
#define GT (NCTA * NTHR)
typedef unsigned long long u64;

// ---------------- device scratch (module globals; allocation-free) ----------------
__device__ float g_Xpre[(size_t)512 * 64 * 3072];  // [t][b][3072] layer-0 x-projection
__device__ float g_H2[(size_t)512 * 64 * 1024];    // [t][b][1024] layer-2 h history
__device__ float g_hbuf[2][3][64 * 1024];          // double-buffered h per layer
__device__ float g_z[3][64 * 1024];                // z gate (wave-local)
__device__ float g_rh[3][64 * 1024];               // r*h (wave-local)
__device__ float g_p1[8][3][64 * 2048];            // zr partials [src*4+kq][l][b*2048+n]
__device__ float g_p2[8][3][64 * 1024];            // g partials
__device__ unsigned g_cnt;
__device__ volatile unsigned g_gen;

// ---------------- helpers ----------------
__device__ __forceinline__ u64 ffma2(u64 a, u64 b, u64 c) {
    u64 d;
    asm("fma.rn.f32x2 %0, %1, %2, %3;" : "=l"(d) : "l"(a), "l"(b), "l"(c));
    return d;
}
__device__ __forceinline__ float psum(u64 a) {
    float2 f = *reinterpret_cast<float2*>(&a);
    return f.x + f.y;
}

__device__ __forceinline__ void gridbar() {
    __syncthreads();
    if (threadIdx.x == 0) {
        unsigned old = g_gen;
        __threadfence();
        if (atomicAdd(&g_cnt, 1u) == NCTA - 1) {
            g_cnt = 0;
            __threadfence();
            g_gen = old + 1;
        } else {
            while (g_gen == old) __nanosleep(64);
            __threadfence();  // acquire: flush L1D so we see other SMs' writes
        }
    }
    __syncthreads();
}

// stage a 64-row x 32-float chunk (row stride lda floats) into XOR-swizzled u64 smem
__device__ __forceinline__ void stage64x32(u64* __restrict__ S, const float* __restrict__ G,
                                           int lda, int tid) {
#pragma unroll
    for (int it = 0; it < 8; ++it) {
        int idx = tid + NTHR * it;
        int row = idx >> 4, k8 = idx & 15;
        u64 v = *reinterpret_cast<const u64*>(G + (size_t)row * lda + (k8 << 1));
        S[(row << 4) + (k8 ^ ((row >> 2) & 15))] = v;
    }
}

// C[64 x 64] (+bias) = A[64 x 32*nch] * W[64 rows x 32*nch]^T ; 128 threads, 8x4 micro
__device__ __forceinline__ void gemm_job(const float* __restrict__ A, int lda,
                                         const float* __restrict__ W, int ldw,
                                         float* __restrict__ C, int cld,
                                         const float* __restrict__ bias, int nch,
                                         u64* __restrict__ Sm) {
    int tid = threadIdx.x, tx = tid & 15, ty = tid >> 4;
    u64 acc[8][4];
#pragma unroll
    for (int i = 0; i < 8; i++)
#pragma unroll
        for (int j = 0; j < 4; j++) acc[i][j] = 0ull;
    for (int c = 0; c < nch; c++) {
        u64* As = Sm + (c & 1) * 2048;
        u64* Ws = As + 1024;
        stage64x32(As, A + c * 32, lda, tid);
        stage64x32(Ws, W + c * 32, ldw, tid);
        __syncthreads();
#pragma unroll
        for (int k8 = 0; k8 < 16; k8++) {
            u64 a2[8], b2[4];
#pragma unroll
            for (int i = 0; i < 8; i++) {
                int row = ty * 8 + i;
                a2[i] = As[(row << 4) + (k8 ^ ((row >> 2) & 15))];
            }
#pragma unroll
            for (int j = 0; j < 4; j++) {
                int row = tx * 4 + j;
                b2[j] = Ws[(row << 4) + (k8 ^ (tx & 15))];
            }
#pragma unroll
            for (int i = 0; i < 8; i++)
#pragma unroll
                for (int j = 0; j < 4; j++) acc[i][j] = ffma2(a2[i], b2[j], acc[i][j]);
        }
        __syncthreads();
    }
#pragma unroll
    for (int i = 0; i < 8; i++)
#pragma unroll
        for (int j = 0; j < 4; j++) {
            float v = psum(acc[i][j]);
            if (bias) v += bias[tx * 4 + j];
            C[(size_t)(ty * 8 + i) * cld + tx * 4 + j] = v;
        }
}

// ---------------- kernels ----------------

// Xpre[t][b][n] = x[b][t][:] . Wx0[n][:]   grid (48, 512)
__global__ __launch_bounds__(NTHR, 3) void k_xpre(const float* __restrict__ x,
                                                  const float* __restrict__ Wx0) {
    __shared__ __align__(16) u64 Sm[4096];
    int n0 = blockIdx.x * 64, s = blockIdx.y;
    gemm_job(x + (size_t)s * 128, 512 * 128, Wx0 + (size_t)n0 * 128, 128,
             g_Xpre + (size_t)s * 64 * 3072 + n0, 3072, nullptr, 4, Sm);
}

// persistent wavefront GRU
__global__ __launch_bounds__(NTHR, 3) void k_gru(const float* __restrict__ Wh0,
                                                 const float* __restrict__ Wxr,
                                                 const float* __restrict__ Whr,
                                                 const float* __restrict__ bh0,
                                                 const float* __restrict__ bhr) {
    __shared__ __align__(16) u64 Sm[4096];
    int cta = blockIdx.x, tid = threadIdx.x;
    int gtid = cta * NTHR + tid;

    // zero both h parity buffers
    for (int i = gtid; i < 2 * 3 * 64 * 1024; i += GT) (&g_hbuf[0][0][0])[i] = 0.f;
    gridbar();

    for (int w = 0; w < 514; ++w) {
        int rd = w & 1, wb = rd ^ 1;

        // ---- P1: z,r partial GEMMs. 640 jobs = {l0:32t x4kq, l1/l2:32t x2src x4kq}
        for (int j = cta; j < 640; j += NCTA) {
            int l, r;
            if (j < 128) { l = 0; r = j; }
            else if (j < 384) { l = 1; r = j - 128; }
            else { l = 2; r = j - 384; }
            int t = w - l;
            if (t < 0 || t >= 512) continue;
            int src, tile, kq;
            if (l == 0) { src = 1; tile = r >> 2; kq = r & 3; }
            else { src = r >> 7; int r2 = r & 127; tile = r2 >> 2; kq = r2 & 3; }
            int n0 = tile * 64;
            const float* A = (src == 0) ? g_hbuf[rd][l - 1] : g_hbuf[rd][l];
            const float* W;
            if (l == 0) W = Wh0;
            else W = ((src == 0) ? Wxr : Whr) + (size_t)(l - 1) * 3 * 1024 * 1024;
            W += (size_t)n0 * 1024 + kq * 256;
            A += kq * 256;
            float* C = g_p1[src * 4 + kq][l] + n0;
            gemm_job(A, 1024, W, 1024, C, 2048, nullptr, 8, Sm);
        }
        gridbar();

        // ---- E1: combine -> z, rh
        for (int idx = gtid; idx < 3 * 64 * 2048; idx += GT) {
            int l = idx >> 17;
            int rem = idx & 131071;
            int t = w - l;
            if (t < 0 || t >= 512) continue;
            int b = rem >> 11, n = rem & 2047;
            float v;
            if (l == 0) {
                v = bh0[n] + g_p1[4][0][rem] + g_p1[5][0][rem] + g_p1[6][0][rem] +
                    g_p1[7][0][rem] + g_Xpre[((size_t)t * 64 + b) * 3072 + n];
            } else {
                v = bhr[(l - 1) * 3072 + n];
#pragma unroll
                for (int p = 0; p < 8; p++) v += g_p1[p][l][rem];
            }
            float s = 1.f / (1.f + __expf(-v));
            if (n < 1024) {
                g_z[l][b * 1024 + n] = s;
            } else {
                int nn = n - 1024;
                g_rh[l][b * 1024 + nn] = s * g_hbuf[rd][l][b * 1024 + nn];
            }
        }
        gridbar();

        // ---- P2: g partial GEMMs. 320 jobs = {l0:16t x4kq, l1/l2:16t x2src x4kq}
        for (int j = cta; j < 320; j += NCTA) {
            int l, r;
            if (j < 64) { l = 0; r = j; }
            else if (j < 192) { l = 1; r = j - 64; }
            else { l = 2; r = j - 192; }
            int t = w - l;
            if (t < 0 || t >= 512) continue;
            int src, tile, kq;
            if (l == 0) { src = 1; tile = r >> 2; kq = r & 3; }
            else { src = r >> 6; int r2 = r & 63; tile = r2 >> 2; kq = r2 & 3; }
            int n0g = 2048 + tile * 64;
            const float* A = (src == 1) ? g_rh[l] : g_hbuf[rd][l - 1];
            const float* W;
            if (l == 0) W = Wh0;
            else W = ((src == 0) ? Wxr : Whr) + (size_t)(l - 1) * 3 * 1024 * 1024;
            W += (size_t)n0g * 1024 + kq * 256;
            A += kq * 256;
            float* C = g_p2[src * 4 + kq][l] + tile * 64;
            gemm_job(A, 1024, W, 1024, C, 1024, nullptr, 8, Sm);
        }
        gridbar();

        // ---- E2: combine -> g, update h, emit H2
        for (int idx = gtid; idx < 3 * 64 * 1024; idx += GT) {
            int l = idx >> 16;
            int rem = idx & 65535;
            int t = w - l;
            if (t < 0 || t >= 512) continue;
            int b = rem >> 10, n = rem & 1023;
            float v;
            if (l == 0) {
                v = bh0[2048 + n] + g_p2[4][0][rem] + g_p2[5][0][rem] + g_p2[6][0][rem] +
                    g_p2[7][0][rem] + g_Xpre[((size_t)t * 64 + b) * 3072 + 2048 + n];
            } else {
                v = bhr[(l - 1) * 3072 + 2048 + n];
#pragma unroll
                for (int p = 0; p < 8; p++) v += g_p2[p][l][rem];
            }
            float g = tanhf(v);
            float z = g_z[l][rem];
            float hp = g_hbuf[rd][l][rem];
            float hn = z * hp + (1.f - z) * g;
            g_hbuf[wb][l][rem] = hn;
            if (l == 2) g_H2[((size_t)t * 64 + b) * 1024 + n] = hn;
        }
        gridbar();
    }
}

// y[b][s][o] = H2[s][b][:] . Wout[o][:] + bout   grid (2, 512)
__global__ __launch_bounds__(NTHR, 3) void k_yout(const float* __restrict__ Wout,
                                                  const float* __restrict__ bout,
                                                  float* __restrict__ out) {
    __shared__ __align__(16) u64 Sm[4096];
    int n0 = blockIdx.x * 64, s = blockIdx.y;
    gemm_job(g_H2 + (size_t)s * 64 * 1024, 1024, Wout + (size_t)n0 * 1024, 1024,
             out + (size_t)s * 128 + n0, 512 * 128, bout + n0, 32, Sm);
}

// hidden_state (B, L, H): layer l's final h sits in parity buffer l&1
__global__ void k_hout(float* __restrict__ out) {
    int i = blockIdx.x * 256 + threadIdx.x;
    if (i >= 3 * 64 * 1024) return;
    int l = i / (64 * 1024);
    int r = i % (64 * 1024);
    int b = r / 1024, n = r % 1024;
    out[(size_t)64 * 512 * 128 + ((size_t)b * 3 + l) * 1024 + n] = g_hbuf[l & 1][l][r];
}

extern "C" void kernel_launch(void* const* d_in, const int* in_sizes, int n_in,
                              void* d_out, int out_size) {
    const float* x = (const float*)d_in[0];
    const float* Wx0 = (const float*)d_in[1];
    const float* Wh0 = (const float*)d_in[2];
    const float* bh0 = (const float*)d_in[3];
    const float* Wxr = (const float*)d_in[4];
    const float* Whr = (const float*)d_in[5];
    const float* bhr = (const float*)d_in[6];
    const float* Wout = (const float*)d_in[7];
    const float* bout = (const float*)d_in[8];
    float* out = (float*)d_out;

    k_xpre<<<dim3(48, 512), NTHR>>>(x, Wx0);
    k_gru<<<NCTA, NTHR>>>(Wh0, Wxr, Whr, bh0, bhr);
    k_yout<<<dim3(2, 512), NTHR>>>(Wout, bout, out);
    k_hout<<<(3 * 64 * 1024 + 255) / 256, 256>>>(out);
}